// round 1
// baseline (speedup 1.0000x reference)
#include <cuda_runtime.h>
#include <cstdint>

// Problem constants
constexpr int BATCH = 2048;
constexpr int DIM   = 1024;
constexpr int MOL   = 8;
constexpr int NPAIR = 28;
constexpr int LQ    = 36;   // MOL + NPAIR
constexpr int OUTD  = 4;

// triu_indices(8,1) in combinations order
__constant__ int c_pi[NPAIR] = {0,0,0,0,0,0,0,1,1,1,1,1,1,2,2,2,2,2,3,3,3,3,4,4,4,5,5,6};
__constant__ int c_pj[NPAIR] = {1,2,3,4,5,6,7,2,3,4,5,6,7,3,4,5,6,7,4,5,6,7,5,6,7,6,7,7};

// Scratch (static device arrays: allocation-free rule)
__device__ float g_WkT[DIM * DIM];                       // 4 MB  : Wk^T
__device__ float g_G[DIM * DIM];                         // 4 MB  : Wq @ Wk^T
__device__ float g_Z[2ull * BATCH * MOL * DIM];          // 128 MB: [PG ; RG]
__device__ float g_w[2 * BATCH * MOL];                   // effective pooling weights

// ---------------------------------------------------------------------------
// packed f32x2 helpers (Blackwell FFMA2 path)
// ---------------------------------------------------------------------------
__device__ __forceinline__ void ffma2(unsigned long long& c,
                                      unsigned long long a,
                                      unsigned long long b) {
    asm("fma.rn.f32x2 %0, %1, %2, %0;" : "+l"(c) : "l"(a), "l"(b));
}
__device__ __forceinline__ unsigned long long dup2(float a) {
    unsigned long long r;
    asm("mov.b64 %0, {%1, %1};" : "=l"(r) : "f"(a));
    return r;
}
__device__ __forceinline__ float lo32(unsigned long long v) {
    return __uint_as_float((unsigned)v);
}
__device__ __forceinline__ float hi32(unsigned long long v) {
    return __uint_as_float((unsigned)(v >> 32));
}

// ---------------------------------------------------------------------------
// Transpose Wk -> g_WkT   (WkT[k][e] = Wk[e][k])
// ---------------------------------------------------------------------------
__global__ void transpose_kernel(const float* __restrict__ src) {
    __shared__ float tile[32][33];
    int tx = threadIdx.x, ty = threadIdx.y;
    int x = blockIdx.x * 32 + tx;
    int y0 = blockIdx.y * 32;
#pragma unroll
    for (int i = ty; i < 32; i += 8)
        tile[i][tx] = src[(size_t)(y0 + i) * DIM + x];
    __syncthreads();
    int x2 = y0 + tx;
#pragma unroll
    for (int i = ty; i < 32; i += 8)
        g_WkT[(size_t)(blockIdx.x * 32 + i) * DIM + x2] = tile[tx][i];
}

// ---------------------------------------------------------------------------
// Tiled NN GEMM (fp32, f32x2 inner product), 128x128x16 tiles, 256 thr, 8x8/thr
//   mode 0: C=g_G   = A(Wq, row-major 1024x1024) @ g_WkT
//   mode 1: C=g_Z   = X @ g_G, X rows gathered:
//           row = s*16384 + b*8 + m ; s==0 -> p_feats[m,b,:], s==1 -> r_feats[m,b,:]
// ---------------------------------------------------------------------------
#define BM 128
#define BN 128
#define BK 16

__global__ void __launch_bounds__(256) gemm_kernel(
    const float* __restrict__ A, int mode,
    const float* __restrict__ src_p, const float* __restrict__ src_r)
{
    __shared__ float As[BK][BM];
    __shared__ float Bs[BK][BN];

    const float* Bmat = mode ? g_G : g_WkT;
    float*       C    = mode ? g_Z : g_G;

    const int tid = threadIdx.x;
    const int tx = tid & 15;      // col group 0..15
    const int ty = tid >> 4;      // row group 0..15
    const int rowBase = blockIdx.x * BM;
    const int colBase = blockIdx.y * BN;

    // per-thread A load assignment (fixed row)
    const int arow = tid >> 1;           // 0..127
    const int acol = (tid & 1) * 8;      // 0 or 8
    const float* aPtr;
    {
        int gr = rowBase + arow;
        if (mode) {
            int s = gr >> 14;
            int b = (gr >> 3) & (BATCH - 1);
            int m = gr & 7;
            const float* src = s ? src_r : src_p;
            aPtr = src + ((size_t)m * BATCH + b) * DIM;
        } else {
            aPtr = A + (size_t)gr * DIM;
        }
    }
    const int brow = tid >> 4;           // 0..15
    const int bcol = (tid & 15) * 8;     // 0..120

    unsigned long long acc[8][4];
#pragma unroll
    for (int i = 0; i < 8; i++)
#pragma unroll
        for (int j = 0; j < 4; j++) acc[i][j] = 0ull;

    for (int k0 = 0; k0 < DIM; k0 += BK) {
        float4 a0 = *(const float4*)(aPtr + k0 + acol);
        float4 a1 = *(const float4*)(aPtr + k0 + acol + 4);
        const float* bp = Bmat + (size_t)(k0 + brow) * DIM + colBase + bcol;
        float4 b0 = *(const float4*)bp;
        float4 b1 = *(const float4*)(bp + 4);

        __syncthreads();
        As[acol + 0][arow] = a0.x; As[acol + 1][arow] = a0.y;
        As[acol + 2][arow] = a0.z; As[acol + 3][arow] = a0.w;
        As[acol + 4][arow] = a1.x; As[acol + 5][arow] = a1.y;
        As[acol + 6][arow] = a1.z; As[acol + 7][arow] = a1.w;
        *(float4*)&Bs[brow][bcol]     = b0;
        *(float4*)&Bs[brow][bcol + 4] = b1;
        __syncthreads();

#pragma unroll
        for (int kk = 0; kk < BK; kk++) {
            float4 af0 = *(const float4*)&As[kk][ty * 8];
            float4 af1 = *(const float4*)&As[kk][ty * 8 + 4];
            union { float4 f; unsigned long long u[2]; } B0, B1;
            B0.f = *(const float4*)&Bs[kk][tx * 8];
            B1.f = *(const float4*)&Bs[kk][tx * 8 + 4];
            float av[8] = {af0.x, af0.y, af0.z, af0.w, af1.x, af1.y, af1.z, af1.w};
#pragma unroll
            for (int i = 0; i < 8; i++) {
                unsigned long long aa = dup2(av[i]);
                ffma2(acc[i][0], aa, B0.u[0]);
                ffma2(acc[i][1], aa, B0.u[1]);
                ffma2(acc[i][2], aa, B1.u[0]);
                ffma2(acc[i][3], aa, B1.u[1]);
            }
        }
    }

#pragma unroll
    for (int i = 0; i < 8; i++) {
        float4 o0, o1;
        o0.x = lo32(acc[i][0]); o0.y = hi32(acc[i][0]);
        o0.z = lo32(acc[i][1]); o0.w = hi32(acc[i][1]);
        o1.x = lo32(acc[i][2]); o1.y = hi32(acc[i][2]);
        o1.z = lo32(acc[i][3]); o1.w = hi32(acc[i][3]);
        size_t crow = (size_t)(rowBase + ty * 8 + i);
        *(float4*)&C[crow * DIM + colBase + tx * 8]     = o0;
        *(float4*)&C[crow * DIM + colBase + tx * 8 + 4] = o1;
    }
}

// ---------------------------------------------------------------------------
// Per-batch attention: 8x8 grams -> 36x36 expand -> softmax -> mean -> att, w
//   side 0: S_r = PG . R^T  -> att_reactant   (queries=p, keys=r)
//   side 1: S_p = RG . P^T  -> att_product
// ---------------------------------------------------------------------------
__global__ void __launch_bounds__(128) att_kernel(
    const float* __restrict__ r_feats, const float* __restrict__ p_feats,
    float* __restrict__ d_out)
{
    const int b = blockIdx.x;
    const int t = threadIdx.x;

    __shared__ float sS[2][MOL][MOL];
    __shared__ float sProb[2][LQ][LQ];   // 10.4 KB
    __shared__ float sAtt[2][LQ];

    // ---- phase 1: 8x8 grams (128 threads = 2 sides x 64 entries) ----
    {
        int side = t >> 6;
        int q = (t >> 3) & 7;
        int k = t & 7;
        const float* zrow = g_Z + (((size_t)side * BATCH + b) * MOL + q) * DIM;
        const float* feats = side ? p_feats : r_feats;
        const float* frow = feats + ((size_t)k * BATCH + b) * DIM;
        float acc0 = 0.f, acc1 = 0.f;
        for (int d = 0; d < DIM; d += 8) {
            float4 z0 = *(const float4*)(zrow + d);
            float4 f0 = *(const float4*)(frow + d);
            float4 z1 = *(const float4*)(zrow + d + 4);
            float4 f1 = *(const float4*)(frow + d + 4);
            acc0 += z0.x * f0.x + z0.y * f0.y + z0.z * f0.z + z0.w * f0.w;
            acc1 += z1.x * f1.x + z1.y * f1.y + z1.z * f1.z + z1.w * f1.w;
        }
        sS[side][q][k] = acc0 + acc1;
    }
    __syncthreads();

    // ---- phase 2: expand to 36x36 rows, softmax over k, store probs ----
    if (t < 2 * LQ) {
        int side = t / LQ;
        int q = t % LQ;
        int qi, qj;
        if (q < MOL) { qi = q; qj = -1; }
        else         { qi = c_pi[q - MOL]; qj = c_pj[q - MOL]; }

        float row[LQ];
        float maxv = -1e30f;
#pragma unroll
        for (int k = 0; k < LQ; k++) {
            int ki, kj;
            if (k < MOL) { ki = k; kj = -1; }
            else         { ki = c_pi[k - MOL]; kj = c_pj[k - MOL]; }
            float v = sS[side][qi][ki];
            if (kj >= 0) v += sS[side][qi][kj];
            if (qj >= 0) {
                v += sS[side][qj][ki];
                if (kj >= 0) v += sS[side][qj][kj];
            }
            v *= 0.03125f;   // 1/sqrt(1024)
            row[k] = v;
            maxv = fmaxf(maxv, v);
        }
        float sum = 0.f;
#pragma unroll
        for (int k = 0; k < LQ; k++) { row[k] = expf(row[k] - maxv); sum += row[k]; }
        float inv = 1.f / sum;
#pragma unroll
        for (int k = 0; k < LQ; k++) sProb[side][q][k] = row[k] * inv;
    }
    __syncthreads();

    // ---- phase 3: mean over queries -> att, write outputs ----
    if (t < 2 * LQ) {
        int side = t / LQ;
        int k = t % LQ;
        float a = 0.f;
#pragma unroll
        for (int q = 0; q < LQ; q++) a += sProb[side][q][k];
        a *= (1.0f / LQ);
        sAtt[side][k] = a;
        // layout: [out (B*4)] [att_reactant (B*36)] [att_product (B*36)]
        d_out[BATCH * OUTD + side * (BATCH * LQ) + b * LQ + k] = a;
    }
    __syncthreads();

    // ---- phase 4: collapse to 8 effective pooling weights per side ----
    if (t < 16) {
        int side = t >> 3;
        int m = t & 7;
        float w = sAtt[side][m];
#pragma unroll
        for (int pp = 0; pp < NPAIR; pp++)
            if (c_pi[pp] == m || c_pj[pp] == m) w += sAtt[side][MOL + pp];
        g_w[side * BATCH * MOL + b * MOL + m] = w;
    }
}

// ---------------------------------------------------------------------------
// Pooling + prediction head (fused): reads the 4 big tensors once.
//   reaction[b,d] = sum_m wr[m]*(r+rn)[m,b,d] - wp[m]*(p+pn)[m,b,d]
//   out[b,o]     = reaction . W_pred[o,:] + b_pred[o]
// ---------------------------------------------------------------------------
__global__ void __launch_bounds__(256) pool_kernel(
    const float* __restrict__ r_feats, const float* __restrict__ p_feats,
    const float* __restrict__ r_new,   const float* __restrict__ p_new,
    const float* __restrict__ W_pred,  const float* __restrict__ b_pred,
    float* __restrict__ d_out)
{
    const int b = blockIdx.x;
    const int t = threadIdx.x;
    __shared__ float sw[16];
    __shared__ float sRed[OUTD][8];
    if (t < 16) sw[t] = g_w[(t >> 3) * BATCH * MOL + b * MOL + (t & 7)];
    __syncthreads();

    float part[OUTD] = {0.f, 0.f, 0.f, 0.f};
    for (int d0 = 0; d0 < DIM; d0 += 256) {
        int d = d0 + t;
        float acc = 0.f;
#pragma unroll
        for (int m = 0; m < MOL; m++) {
            size_t off = ((size_t)m * BATCH + b) * DIM + d;
            acc += sw[m]     * (r_feats[off] + r_new[off]);
            acc -= sw[8 + m] * (p_feats[off] + p_new[off]);
        }
#pragma unroll
        for (int o = 0; o < OUTD; o++) part[o] += acc * W_pred[o * DIM + d];
    }

    int lane = t & 31, wid = t >> 5;
#pragma unroll
    for (int o = 0; o < OUTD; o++) {
        float v = part[o];
#pragma unroll
        for (int off = 16; off > 0; off >>= 1)
            v += __shfl_down_sync(0xFFFFFFFFu, v, off);
        if (lane == 0) sRed[o][wid] = v;
    }
    __syncthreads();
    if (t < OUTD) {
        float s = 0.f;
#pragma unroll
        for (int w = 0; w < 8; w++) s += sRed[t][w];
        d_out[b * OUTD + t] = s + b_pred[t];
    }
}

// ---------------------------------------------------------------------------
extern "C" void kernel_launch(void* const* d_in, const int* in_sizes, int n_in,
                              void* d_out, int out_size) {
    const float* r_feats = (const float*)d_in[0];
    const float* p_feats = (const float*)d_in[1];
    const float* r_new   = (const float*)d_in[2];
    const float* p_new   = (const float*)d_in[3];
    const float* Wq      = (const float*)d_in[4];
    const float* Wk      = (const float*)d_in[5];
    const float* W_pred  = (const float*)d_in[6];
    const float* b_pred  = (const float*)d_in[7];
    float* out = (float*)d_out;

    // 1) WkT
    transpose_kernel<<<dim3(32, 32), dim3(32, 8)>>>(Wk);
    // 2) G = Wq @ Wk^T   (1024x1024x1024)
    gemm_kernel<<<dim3(8, 8), 256>>>(Wq, 0, nullptr, nullptr);
    // 3) Z = [P;R] @ G   (32768x1024x1024) — the dominant GEMM
    gemm_kernel<<<dim3(256, 8), 256>>>(nullptr, 1, p_feats, r_feats);
    // 4) grams -> softmax -> att outputs + pooling weights
    att_kernel<<<BATCH, 128>>>(r_feats, p_feats, out);
    // 5) pooling + head
    pool_kernel<<<BATCH, 256>>>(r_feats, p_feats, r_new, p_new, W_pred, b_pred, out);
}